// round 14
// baseline (speedup 1.0000x reference)
#include <cuda_runtime.h>
#include <cuda_bf16.h>
#include <cstdint>

#define NB 256
#define NS 512
#define ND 256
#define NA 128
#define TM 64                // CTA tile rows
#define NTILE2 (NS / TM)     // 8
#define KC 32
#define NCHUNK (ND / KC)     // 8
#define ASTR 40              // bf16 row stride (elems) = 80B, ldmatrix conflict-free

// ---- scratch (allocation-free rule: device globals) ----
__device__ float g_part[NB * NTILE2 * ND];
__device__ float g_esum[NB * NTILE2];
__device__ __nv_bfloat16 g_wt_hi[NA * ND];   // [n][k] K-major
__device__ __nv_bfloat16 g_wt_lo[NA * ND];

// ---- smem layout (bytes) ----
#define S_ES   0                              // 64 floats
#define S_BSM  512
#define S_USM  1024
#define S_RED  1536                           // 64 floats
#define S_AH(b) (2048 + (b) * 10240)          // 64 rows * 80B, hi
#define S_AL(b) (S_AH(b) + 5120)              // lo
#define S_BH(b) (22528 + (b) * 20480)         // 128 n * 80B, hi
#define S_BL(b) (S_BH(b) + 10240)             // lo
#define SMEM_TOTAL 63488                      // fits 3 CTAs/SM (190 KB <= 228)

#define LDSM4(r, addr) \
    asm volatile("ldmatrix.sync.aligned.m8n8.x4.shared.b16 {%0,%1,%2,%3}, [%4];" \
        : "=r"((r)[0]), "=r"((r)[1]), "=r"((r)[2]), "=r"((r)[3]) : "r"(addr))

#define MMA16816(d, a, b0, b1) \
    asm volatile("mma.sync.aligned.m16n8k16.row.col.f32.bf16.bf16.f32 " \
        "{%0,%1,%2,%3},{%4,%5,%6,%7},{%8,%9},{%0,%1,%2,%3};" \
        : "+f"((d)[0]), "+f"((d)[1]), "+f"((d)[2]), "+f"((d)[3]) \
        : "r"((a)[0]), "r"((a)[1]), "r"((a)[2]), "r"((a)[3]), "r"(b0), "r"(b1))

__device__ __forceinline__ void cp16(char* dst, const char* src) {
    unsigned saddr = (unsigned)__cvta_generic_to_shared(dst);
    asm volatile("cp.async.cg.shared.global [%0], [%1], 16;\n" :: "r"(saddr), "l"(src));
}
__device__ __forceinline__ void cp_commit() { asm volatile("cp.async.commit_group;\n"); }
template<int N> __device__ __forceinline__ void cp_wait() {
    asm volatile("cp.async.wait_group %0;\n" :: "n"(N));
}
__device__ __forceinline__ uint32_t pack_bf2(float a, float b) {
    __nv_bfloat162 t = __halves2bfloat162(__float2bfloat16(a), __float2bfloat16(b));
    return *(uint32_t*)&t;
}
__device__ __forceinline__ float bf_res(float v) {
    return v - __bfloat162float(__float2bfloat16(v));
}
__device__ __forceinline__ float fast_tanh(float x) {
    float e = __expf(2.0f * x);
    return 1.0f - __fdividef(2.0f, e + 1.0f);
}

// ---------------------------------------------------------------------------
__global__ void __launch_bounds__(256) wprep_kernel(const float* __restrict__ W) {
    int idx = blockIdx.x * 256 + threadIdx.x;
    if (idx < ND * NA) {
        int k = idx >> 7;
        int n = idx & (NA - 1);
        float w = W[idx];
        __nv_bfloat16 h = __float2bfloat16(w);
        g_wt_hi[n * ND + k] = h;
        g_wt_lo[n * ND + k] = __float2bfloat16(w - __bfloat162float(h));
    }
}

// ---------------------------------------------------------------------------
// 64x128 CTA tile, warp tile 16x64 (round-6 verified H engine), occ 3.
// ---------------------------------------------------------------------------
__global__ void __launch_bounds__(256, 3) scores_kernel(
    const float* __restrict__ x, const float* __restrict__ bias,
    const float* __restrict__ u)
{
    extern __shared__ char smem[];
    const uint32_t smb = (uint32_t)__cvta_generic_to_shared(smem);

    const int b    = blockIdx.y;
    const int tile = blockIdx.x;          // 0..7
    const int tid  = threadIdx.x;
    const int w    = tid >> 5;
    const int l    = tid & 31;
    const int wm   = w >> 1;              // rows wm*16
    const int wn   = w & 1;               // cols wn*64

    float* es  = (float*)(smem + S_ES);
    float* bsm = (float*)(smem + S_BSM);
    float* usm = (float*)(smem + S_USM);
    float* red = (float*)(smem + S_RED);

    if (tid < NA) { bsm[tid] = bias[tid]; usm[tid] = u[tid]; }
    if (tid < TM) red[tid] = 0.0f;

    const float* xb = x + ((size_t)b * NS + tile * TM) * ND;

    // ---- A staging: 4 threads/row over 64 rows, LDG->split->STS ----
    const int xrow = tid >> 2, xseg = tid & 3;
    float4 st[2];
    auto load_x = [&](int c) {
        const float* p = xb + (size_t)xrow * ND + c * KC + xseg * 8;
        st[0] = ((const float4*)p)[0];
        st[1] = ((const float4*)p)[1];
    };
    auto sts_x = [&](int buf) {
        uint32_t hv[4], lv[4];
#pragma unroll
        for (int i = 0; i < 2; i++) {
            float vs[4] = { st[i].x, st[i].y, st[i].z, st[i].w };
            hv[2*i]   = pack_bf2(vs[0], vs[1]);
            hv[2*i+1] = pack_bf2(vs[2], vs[3]);
            lv[2*i]   = pack_bf2(bf_res(vs[0]), bf_res(vs[1]));
            lv[2*i+1] = pack_bf2(bf_res(vs[2]), bf_res(vs[3]));
        }
        int off = xrow * (ASTR * 2) + xseg * 16;
        *(uint4*)(smem + S_AH(buf) + off) = make_uint4(hv[0], hv[1], hv[2], hv[3]);
        *(uint4*)(smem + S_AL(buf) + off) = make_uint4(lv[0], lv[1], lv[2], lv[3]);
    };
    auto cp_w = [&](int c, int buf) {
#pragma unroll
        for (int it = 0; it < 4; it++) {
            int idx = tid + it * 256;
            int h = idx >> 9, rem = idx & 511;
            int n = rem >> 2, s = rem & 3;
            const char* src = (const char*)(h ? g_wt_lo : g_wt_hi)
                              + (size_t)n * (ND * 2) + c * (KC * 2) + s * 16;
            cp16(smem + (h ? S_BL(buf) : S_BH(buf)) + n * (ASTR * 2) + s * 16, src);
        }
        cp_commit();
    };

    float acc[8][4];
#pragma unroll
    for (int nf = 0; nf < 8; nf++)
#pragma unroll
        for (int e = 0; e < 4; e++) acc[nf][e] = 0.0f;

    const uint32_t lane_off = (uint32_t)((l & 15) * (ASTR * 2) + (l >> 4) * 16);

    load_x(0);
    cp_w(0, 0);
    sts_x(0);

#pragma unroll 1
    for (int c = 0; c < NCHUNK; c++) {
        const int buf = c & 1;
        if (c < NCHUNK - 1) { cp_w(c + 1, buf ^ 1); load_x(c + 1); cp_wait<1>(); }
        else cp_wait<0>();
        __syncthreads();

        const uint32_t ah_base = smb + S_AH(buf) + (uint32_t)(wm * 16) * (ASTR * 2) + lane_off;
        const uint32_t al_base = smb + S_AL(buf) + (uint32_t)(wm * 16) * (ASTR * 2) + lane_off;
        const uint32_t bh_base = smb + S_BH(buf) + (uint32_t)(wn * 64) * (ASTR * 2) + lane_off;
        const uint32_t bl_base = smb + S_BL(buf) + (uint32_t)(wn * 64) * (ASTR * 2) + lane_off;

#pragma unroll
        for (int kk = 0; kk < KC; kk += 16) {
            uint32_t ah[4], al[4];
            LDSM4(ah, ah_base + kk * 2);
            LDSM4(al, al_base + kk * 2);
#pragma unroll
            for (int np = 0; np < 4; np++) {
                uint32_t bh[4], bl[4];
                LDSM4(bh, bh_base + np * 16 * (ASTR * 2) + kk * 2);
                LDSM4(bl, bl_base + np * 16 * (ASTR * 2) + kk * 2);
#pragma unroll
                for (int sn = 0; sn < 2; sn++) {
                    float* d = acc[np * 2 + sn];
                    uint32_t h0 = sn ? bh[1] : bh[0], h1 = sn ? bh[3] : bh[2];
                    uint32_t l0 = sn ? bl[1] : bl[0], l1 = sn ? bl[3] : bl[2];
                    MMA16816(d, ah, h0, h1);
                    MMA16816(d, ah, l0, l1);
                    MMA16816(d, al, h0, h1);
                }
            }
        }
        if (c < NCHUNK - 1) sts_x(buf ^ 1);
        __syncthreads();
    }

    // ---- epilogue: tanh + dot(u) -> logits (rows wm*16+g, +8) ----
    {
        const int g = l >> 2, tig = l & 3;
        float pA = 0.0f, pB = 0.0f;
#pragma unroll
        for (int nf = 0; nf < 8; nf++)
#pragma unroll
            for (int e = 0; e < 2; e++) {
                int col = wn * 64 + nf * 8 + 2 * tig + e;
                pA += fast_tanh(acc[nf][e]     + bsm[col]) * usm[col];
                pB += fast_tanh(acc[nf][2 + e] + bsm[col]) * usm[col];
            }
        pA += __shfl_xor_sync(0xffffffffu, pA, 1);
        pA += __shfl_xor_sync(0xffffffffu, pA, 2);
        pB += __shfl_xor_sync(0xffffffffu, pB, 1);
        pB += __shfl_xor_sync(0xffffffffu, pB, 2);
        if (tig == 0) {
            atomicAdd(&red[wm * 16 + g], pA);      // exactly 2 contributors/row
            atomicAdd(&red[wm * 16 + 8 + g], pB);
        }
    }
    __syncthreads();
    if (tid < TM) es[tid] = expf(red[tid]);        // faithful: no max-subtraction
    __syncthreads();

    // tile exp-sum over 64 rows (deterministic tree)
    if (tid < 32) {
        float v = es[tid] + es[tid + 32];
#pragma unroll
        for (int off = 16; off > 0; off >>= 1)
            v += __shfl_down_sync(0xffffffffu, v, off);
        if (tid == 0) g_esum[b * NTILE2 + tile] = v;
    }

    // weighted partial sum over this tile's 64 rows (x L2-hot)
    float a0 = 0.f, a1 = 0.f, a2 = 0.f, a3 = 0.f;
#pragma unroll 4
    for (int s = 0; s < TM; s += 4) {
        a0 += es[s + 0] * xb[(size_t)(s + 0) * ND + tid];
        a1 += es[s + 1] * xb[(size_t)(s + 1) * ND + tid];
        a2 += es[s + 2] * xb[(size_t)(s + 2) * ND + tid];
        a3 += es[s + 3] * xb[(size_t)(s + 3) * ND + tid];
    }
    g_part[((size_t)b * NTILE2 + tile) * ND + tid] = (a0 + a1) + (a2 + a3);
}

// ---------------------------------------------------------------------------
__global__ void __launch_bounds__(256) finish_kernel(float* __restrict__ out)
{
    const int b = blockIdx.x;
    const int tid = threadIdx.x;
    float s = 0.f;
#pragma unroll
    for (int t = 0; t < NTILE2; t++) s += g_esum[b * NTILE2 + t];
    const float inv = 1.0f / (s + 1e-8f);
    float v = 0.f;
#pragma unroll
    for (int t = 0; t < NTILE2; t++) v += g_part[((size_t)b * NTILE2 + t) * ND + tid];
    out[b * ND + tid] = v * inv;
}

extern "C" void kernel_launch(void* const* d_in, const int* in_sizes, int n_in,
                              void* d_out, int out_size) {
    const float* x    = (const float*)d_in[0];
    const float* W    = (const float*)d_in[1];
    const float* bias = (const float*)d_in[2];
    const float* u    = (const float*)d_in[3];
    float* out        = (float*)d_out;

    cudaFuncSetAttribute(scores_kernel, cudaFuncAttributeMaxDynamicSharedMemorySize, SMEM_TOTAL);

    wprep_kernel<<<(ND * NA + 255) / 256, 256>>>(W);
    scores_kernel<<<dim3(NTILE2, NB), 256, SMEM_TOTAL>>>(x, bias, u);
    finish_kernel<<<NB, 256>>>(out);
}

// round 15
// speedup vs baseline: 1.0722x; 1.0722x over previous
#include <cuda_runtime.h>
#include <cuda_bf16.h>
#include <cstdint>

#define NB 256
#define NS 512
#define ND 256
#define NA 128
#define TS 128
#define NTILE (NS / TS)     // 4
#define KC 32
#define NCHUNK (ND / KC)    // 8
#define ASTR 40             // bf16 row stride (elems) = 80B, ldmatrix conflict-free

// ---- scratch (allocation-free rule: device globals) ----
__device__ float g_part[NB * NTILE * ND];
__device__ float g_esum[NB * NTILE];
__device__ __nv_bfloat16 g_wt_hi[NA * ND];   // [n][k] K-major
__device__ __nv_bfloat16 g_wt_lo[NA * ND];

// ---- smem layout (bytes), identical to round 4 ----
#define H_ES    0
#define H_BSM   512
#define H_USM   1024
#define H_RED   1536
#define H_TILES 2048
#define HTILE_B (TS * ASTR * 2)          // 10240
#define H_AH(buf) (H_TILES + (buf) * 4 * HTILE_B + 0 * HTILE_B)
#define H_AL(buf) (H_TILES + (buf) * 4 * HTILE_B + 1 * HTILE_B)
#define H_BH(buf) (H_TILES + (buf) * 4 * HTILE_B + 2 * HTILE_B)
#define H_BL(buf) (H_TILES + (buf) * 4 * HTILE_B + 3 * HTILE_B)
#define SMEM_TOTAL (H_TILES + 8 * HTILE_B)   // 83968

#define LDSM4(r, addr) \
    asm volatile("ldmatrix.sync.aligned.m8n8.x4.shared.b16 {%0,%1,%2,%3}, [%4];" \
        : "=r"((r)[0]), "=r"((r)[1]), "=r"((r)[2]), "=r"((r)[3]) : "r"(addr))

#define MMA16816(d, a, b0, b1) \
    asm volatile("mma.sync.aligned.m16n8k16.row.col.f32.bf16.bf16.f32 " \
        "{%0,%1,%2,%3},{%4,%5,%6,%7},{%8,%9},{%0,%1,%2,%3};" \
        : "+f"((d)[0]), "+f"((d)[1]), "+f"((d)[2]), "+f"((d)[3]) \
        : "r"((a)[0]), "r"((a)[1]), "r"((a)[2]), "r"((a)[3]), "r"(b0), "r"(b1))

__device__ __forceinline__ void cp16(char* dst, const char* src) {
    unsigned saddr = (unsigned)__cvta_generic_to_shared(dst);
    asm volatile("cp.async.cg.shared.global [%0], [%1], 16;\n" :: "r"(saddr), "l"(src));
}
__device__ __forceinline__ void cp_commit() { asm volatile("cp.async.commit_group;\n"); }
template<int N> __device__ __forceinline__ void cp_wait() {
    asm volatile("cp.async.wait_group %0;\n" :: "n"(N));
}
__device__ __forceinline__ uint32_t pack_bf2(float a, float b) {
    __nv_bfloat162 t = __halves2bfloat162(__float2bfloat16(a), __float2bfloat16(b));
    return *(uint32_t*)&t;
}
__device__ __forceinline__ float fast_tanh(float x) {
    float e = __expf(2.0f * x);
    return 1.0f - __fdividef(2.0f, e + 1.0f);
}

// ---------------------------------------------------------------------------
__global__ void __launch_bounds__(256) wprep_kernel(const float* __restrict__ W) {
    int idx = blockIdx.x * 256 + threadIdx.x;
    if (idx < ND * NA) {
        int k = idx >> 7;
        int n = idx & (NA - 1);
        float w = W[idx];
        __nv_bfloat16 h = __float2bfloat16(w);
        g_wt_hi[n * ND + k] = h;
        g_wt_lo[n * ND + k] = __float2bfloat16(w - __bfloat162float(h));
    }
}

// ---------------------------------------------------------------------------
// Round-4 engine with ONE change: single barrier per chunk.  Next-chunk
// staging (cp_w / load_x / sts_x) issues strictly AFTER the top barrier,
// so the bottom barrier is redundant and removed.
// ---------------------------------------------------------------------------
__global__ void __launch_bounds__(256, 2) scores_kernel(
    const float* __restrict__ x, const float* __restrict__ bias,
    const float* __restrict__ u)
{
    extern __shared__ char smem[];
    const uint32_t smb = (uint32_t)__cvta_generic_to_shared(smem);

    const int b    = blockIdx.y;
    const int tile = blockIdx.x;
    const int s0   = tile * TS;
    const int tid  = threadIdx.x;
    const int w    = tid >> 5;
    const int l    = tid & 31;
    const int wm   = w >> 1;       // rows wm*32
    const int wn   = w & 1;        // cols wn*64

    float* es  = (float*)(smem + H_ES);
    float* bsm = (float*)(smem + H_BSM);
    float* usm = (float*)(smem + H_USM);
    float* red = (float*)(smem + H_RED);

    if (tid < NA) { bsm[tid] = bias[tid]; usm[tid] = u[tid]; }
    if (tid < TS) red[tid] = 0.0f;

    const float* xb = x + ((size_t)b * NS + s0) * ND;

    // ---- A staging: 2 threads/row, LDG->split->STS (round-4 verified) ----
    const int xrow = tid >> 1, xcolh = tid & 1;
    float4 st[4];
    auto load_x = [&](int c) {
        const float* p = xb + (size_t)xrow * ND + c * KC + xcolh * 16;
#pragma unroll
        for (int i = 0; i < 4; i++) st[i] = ((const float4*)p)[i];
    };
    auto sts_x = [&](int buf) {
        uint32_t hv[8], lv[8];
#pragma unroll
        for (int i = 0; i < 4; i++) {
            float vs[4] = { st[i].x, st[i].y, st[i].z, st[i].w };
            float ls[4];
#pragma unroll
            for (int j = 0; j < 4; j++) {
                __nv_bfloat16 h = __float2bfloat16(vs[j]);
                ls[j] = vs[j] - __bfloat162float(h);
            }
            hv[2*i]   = pack_bf2(vs[0], vs[1]);
            hv[2*i+1] = pack_bf2(vs[2], vs[3]);
            lv[2*i]   = pack_bf2(ls[0], ls[1]);
            lv[2*i+1] = pack_bf2(ls[2], ls[3]);
        }
        int off = xrow * (ASTR * 2) + xcolh * 32;
        *(uint4*)(smem + H_AH(buf) + off)      = make_uint4(hv[0], hv[1], hv[2], hv[3]);
        *(uint4*)(smem + H_AH(buf) + off + 16) = make_uint4(hv[4], hv[5], hv[6], hv[7]);
        *(uint4*)(smem + H_AL(buf) + off)      = make_uint4(lv[0], lv[1], lv[2], lv[3]);
        *(uint4*)(smem + H_AL(buf) + off + 16) = make_uint4(lv[4], lv[5], lv[6], lv[7]);
    };
    auto cp_w = [&](int c, int buf) {
#pragma unroll
        for (int it = 0; it < 4; it++) {
            int idx = tid + it * 256;
            int h = idx >> 9, rem = idx & 511;
            int n = rem >> 2, s = rem & 3;
            const char* src = (const char*)(h ? g_wt_lo : g_wt_hi) + (size_t)n * (ND * 2) + c * (KC * 2) + s * 16;
            cp16(smem + (h ? H_BL(buf) : H_BH(buf)) + n * (ASTR * 2) + s * 16, src);
        }
        cp_commit();
    };

    float acc[2][8][4];
#pragma unroll
    for (int m = 0; m < 2; m++)
#pragma unroll
        for (int nf = 0; nf < 8; nf++)
#pragma unroll
            for (int e = 0; e < 4; e++) acc[m][nf][e] = 0.0f;

    const uint32_t lane_off = (uint32_t)((l & 15) * (ASTR * 2) + (l >> 4) * 16);

    // ---- prologue: group 0 in flight; A(0) staged ----
    load_x(0);
    cp_w(0, 0);
    sts_x(0);

#pragma unroll 1
    for (int c = 0; c < NCHUNK; c++) {
        const int buf = c & 1;
        cp_wait<0>();          // drain group c (the only outstanding one)
        __syncthreads();       // B(c)+A(c) visible; all iter c-1 reads retired
        if (c < NCHUNK - 1) {  // stage chunk c+1 AFTER the barrier: race-free
            cp_w(c + 1, buf ^ 1);
            load_x(c + 1);
        }

        const uint32_t ah_base = smb + H_AH(buf) + (uint32_t)(wm * 32) * (ASTR * 2) + lane_off;
        const uint32_t al_base = smb + H_AL(buf) + (uint32_t)(wm * 32) * (ASTR * 2) + lane_off;
        const uint32_t bh_base = smb + H_BH(buf) + (uint32_t)(wn * 64) * (ASTR * 2) + lane_off;
        const uint32_t bl_base = smb + H_BL(buf) + (uint32_t)(wn * 64) * (ASTR * 2) + lane_off;

#pragma unroll
        for (int kk = 0; kk < KC; kk += 16) {
            uint32_t ah[2][4], al[2][4];
#pragma unroll
            for (int m = 0; m < 2; m++) {
                LDSM4(ah[m], ah_base + m * 16 * (ASTR * 2) + kk * 2);
                LDSM4(al[m], al_base + m * 16 * (ASTR * 2) + kk * 2);
            }
#pragma unroll
            for (int np = 0; np < 4; np++) {
                uint32_t bh[4], bl[4];
                LDSM4(bh, bh_base + np * 16 * (ASTR * 2) + kk * 2);
                LDSM4(bl, bl_base + np * 16 * (ASTR * 2) + kk * 2);
#pragma unroll
                for (int m = 0; m < 2; m++)
#pragma unroll
                    for (int sn = 0; sn < 2; sn++) {
                        float* d = acc[m][np * 2 + sn];
                        uint32_t h0 = sn ? bh[1] : bh[0], h1 = sn ? bh[3] : bh[2];
                        uint32_t l0 = sn ? bl[1] : bl[0], l1 = sn ? bl[3] : bl[2];
                        MMA16816(d, ah[m], h0, h1);
                        MMA16816(d, ah[m], l0, l1);
                        MMA16816(d, al[m], h0, h1);
                    }
            }
        }
        if (c < NCHUNK - 1) sts_x(buf ^ 1);   // A(c+1): readers gated by next top barrier
    }

    // ---- epilogue: tanh + dot(u) ----
    __syncthreads();     // all mainloop smem reads done before red/es reuse
    const int g = l >> 2, tig = l & 3;
#pragma unroll
    for (int m = 0; m < 2; m++) {
        float pA = 0.0f, pB = 0.0f;
#pragma unroll
        for (int nf = 0; nf < 8; nf++)
#pragma unroll
            for (int e = 0; e < 2; e++) {
                int col = wn * 64 + nf * 8 + 2 * tig + e;
                pA += fast_tanh(acc[m][nf][e]     + bsm[col]) * usm[col];
                pB += fast_tanh(acc[m][nf][2 + e] + bsm[col]) * usm[col];
            }
        pA += __shfl_xor_sync(0xffffffffu, pA, 1);
        pA += __shfl_xor_sync(0xffffffffu, pA, 2);
        pB += __shfl_xor_sync(0xffffffffu, pB, 1);
        pB += __shfl_xor_sync(0xffffffffu, pB, 2);
        if (tig == 0) {
            int row = wm * 32 + m * 16 + g;
            atomicAdd(&red[row], pA);          // exactly 2 contributors/row
            atomicAdd(&red[row + 8], pB);
        }
    }
    __syncthreads();
    if (tid < TS) es[tid] = expf(red[tid]);    // faithful: no max-subtraction
    __syncthreads();

    // tile exp-sum (deterministic tree)
    if (tid < 64) red[tid] = es[tid] + es[tid + 64];
    __syncthreads();
    if (tid < 32) {
        float v = red[tid] + red[tid + 32];
#pragma unroll
        for (int off = 16; off > 0; off >>= 1)
            v += __shfl_down_sync(0xffffffffu, v, off);
        if (tid == 0) g_esum[b * NTILE + tile] = v;
    }

    // weighted partial sum over tile rows (x L2-hot)
    float a0 = 0.f, a1 = 0.f, a2 = 0.f, a3 = 0.f;
#pragma unroll 4
    for (int s = 0; s < TS; s += 4) {
        a0 += es[s + 0] * xb[(size_t)(s + 0) * ND + tid];
        a1 += es[s + 1] * xb[(size_t)(s + 1) * ND + tid];
        a2 += es[s + 2] * xb[(size_t)(s + 2) * ND + tid];
        a3 += es[s + 3] * xb[(size_t)(s + 3) * ND + tid];
    }
    g_part[((size_t)b * NTILE + tile) * ND + tid] = (a0 + a1) + (a2 + a3);
}

// ---------------------------------------------------------------------------
__global__ void __launch_bounds__(256) finish_kernel(float* __restrict__ out)
{
    const int b = blockIdx.x;
    const int tid = threadIdx.x;
    float s = 0.f;
#pragma unroll
    for (int t = 0; t < NTILE; t++) s += g_esum[b * NTILE + t];
    const float inv = 1.0f / (s + 1e-8f);
    float v = 0.f;
#pragma unroll
    for (int t = 0; t < NTILE; t++) v += g_part[((size_t)b * NTILE + t) * ND + tid];
    out[b * ND + tid] = v * inv;
}

extern "C" void kernel_launch(void* const* d_in, const int* in_sizes, int n_in,
                              void* d_out, int out_size) {
    const float* x    = (const float*)d_in[0];
    const float* W    = (const float*)d_in[1];
    const float* bias = (const float*)d_in[2];
    const float* u    = (const float*)d_in[3];
    float* out        = (float*)d_out;

    cudaFuncSetAttribute(scores_kernel, cudaFuncAttributeMaxDynamicSharedMemorySize, SMEM_TOTAL);

    wprep_kernel<<<(ND * NA + 255) / 256, 256>>>(W);
    scores_kernel<<<dim3(NTILE, NB), 256, SMEM_TOTAL>>>(x, bias, u);
    finish_kernel<<<NB, 256>>>(out);
}

// round 16
// speedup vs baseline: 1.0936x; 1.0200x over previous
#include <cuda_runtime.h>
#include <cuda_bf16.h>
#include <cstdint>

#define NB 256
#define NS 512
#define ND 256
#define NA 128
#define TS 128
#define NTILE (NS / TS)     // 4
#define KC 32
#define NCHUNK (ND / KC)    // 8
#define ASTR 40             // bf16 row stride (elems) = 80B, ldmatrix conflict-free

// ---- scratch (allocation-free rule: device globals) ----
__device__ float g_part[NB * NTILE * ND];
__device__ float g_esum[NB * NTILE];
__device__ __nv_bfloat16 g_wt_hi[NA * ND];   // [n][k] K-major
__device__ __nv_bfloat16 g_wt_lo[NA * ND];

// ---- smem layout (bytes), identical to round 4/15 ----
#define H_ES    0
#define H_BSM   512
#define H_USM   1024
#define H_RED   1536
#define H_TILES 2048
#define HTILE_B (TS * ASTR * 2)          // 10240
#define H_AH(buf) (H_TILES + (buf) * 4 * HTILE_B + 0 * HTILE_B)
#define H_AL(buf) (H_TILES + (buf) * 4 * HTILE_B + 1 * HTILE_B)
#define H_BH(buf) (H_TILES + (buf) * 4 * HTILE_B + 2 * HTILE_B)
#define H_BL(buf) (H_TILES + (buf) * 4 * HTILE_B + 3 * HTILE_B)
#define SMEM_TOTAL (H_TILES + 8 * HTILE_B)   // 83968

#define LDSM4(r, addr) \
    asm volatile("ldmatrix.sync.aligned.m8n8.x4.shared.b16 {%0,%1,%2,%3}, [%4];" \
        : "=r"((r)[0]), "=r"((r)[1]), "=r"((r)[2]), "=r"((r)[3]) : "r"(addr))

#define MMA16816(d, a, b0, b1) \
    asm volatile("mma.sync.aligned.m16n8k16.row.col.f32.bf16.bf16.f32 " \
        "{%0,%1,%2,%3},{%4,%5,%6,%7},{%8,%9},{%0,%1,%2,%3};" \
        : "+f"((d)[0]), "+f"((d)[1]), "+f"((d)[2]), "+f"((d)[3]) \
        : "r"((a)[0]), "r"((a)[1]), "r"((a)[2]), "r"((a)[3]), "r"(b0), "r"(b1))

__device__ __forceinline__ void cp16(char* dst, const char* src) {
    unsigned saddr = (unsigned)__cvta_generic_to_shared(dst);
    asm volatile("cp.async.cg.shared.global [%0], [%1], 16;\n" :: "r"(saddr), "l"(src));
}
__device__ __forceinline__ void cp_commit() { asm volatile("cp.async.commit_group;\n"); }
template<int N> __device__ __forceinline__ void cp_wait() {
    asm volatile("cp.async.wait_group %0;\n" :: "n"(N));
}
__device__ __forceinline__ uint32_t pack_bf2(float a, float b) {
    __nv_bfloat162 t = __halves2bfloat162(__float2bfloat16(a), __float2bfloat16(b));
    return *(uint32_t*)&t;
}
__device__ __forceinline__ float fast_tanh(float x) {
    float e = __expf(2.0f * x);
    return 1.0f - __fdividef(2.0f, e + 1.0f);
}

// ---------------------------------------------------------------------------
__global__ void __launch_bounds__(256) wprep_kernel(const float* __restrict__ W) {
    int idx = blockIdx.x * 256 + threadIdx.x;
    if (idx < ND * NA) {
        int k = idx >> 7;
        int n = idx & (NA - 1);
        float w = W[idx];
        __nv_bfloat16 h = __float2bfloat16(w);
        g_wt_hi[n * ND + k] = h;
        g_wt_lo[n * ND + k] = __float2bfloat16(w - __bfloat162float(h));
    }
#if __CUDA_ARCH__ >= 900
    cudaTriggerProgrammaticLaunchCompletion();
#endif
}

// ---------------------------------------------------------------------------
// Round-4/15 engine + PDL: W-independent prologue overlaps wprep; trigger
// lets finish launch during the tail.
// ---------------------------------------------------------------------------
__global__ void __launch_bounds__(256, 2) scores_kernel(
    const float* __restrict__ x, const float* __restrict__ bias,
    const float* __restrict__ u)
{
    extern __shared__ char smem[];
    const uint32_t smb = (uint32_t)__cvta_generic_to_shared(smem);

    const int b    = blockIdx.y;
    const int tile = blockIdx.x;
    const int s0   = tile * TS;
    const int tid  = threadIdx.x;
    const int w    = tid >> 5;
    const int l    = tid & 31;
    const int wm   = w >> 1;       // rows wm*32
    const int wn   = w & 1;        // cols wn*64

    float* es  = (float*)(smem + H_ES);
    float* bsm = (float*)(smem + H_BSM);
    float* usm = (float*)(smem + H_USM);
    float* red = (float*)(smem + H_RED);

    if (tid < NA) { bsm[tid] = bias[tid]; usm[tid] = u[tid]; }
    if (tid < TS) red[tid] = 0.0f;

    const float* xb = x + ((size_t)b * NS + s0) * ND;

    // ---- A staging: 2 threads/row, LDG->split->STS (round-4 verified) ----
    const int xrow = tid >> 1, xcolh = tid & 1;
    float4 st[4];
    auto load_x = [&](int c) {
        const float* p = xb + (size_t)xrow * ND + c * KC + xcolh * 16;
#pragma unroll
        for (int i = 0; i < 4; i++) st[i] = ((const float4*)p)[i];
    };
    auto sts_x = [&](int buf) {
        uint32_t hv[8], lv[8];
#pragma unroll
        for (int i = 0; i < 4; i++) {
            float vs[4] = { st[i].x, st[i].y, st[i].z, st[i].w };
            float ls[4];
#pragma unroll
            for (int j = 0; j < 4; j++) {
                __nv_bfloat16 h = __float2bfloat16(vs[j]);
                ls[j] = vs[j] - __bfloat162float(h);
            }
            hv[2*i]   = pack_bf2(vs[0], vs[1]);
            hv[2*i+1] = pack_bf2(vs[2], vs[3]);
            lv[2*i]   = pack_bf2(ls[0], ls[1]);
            lv[2*i+1] = pack_bf2(ls[2], ls[3]);
        }
        int off = xrow * (ASTR * 2) + xcolh * 32;
        *(uint4*)(smem + H_AH(buf) + off)      = make_uint4(hv[0], hv[1], hv[2], hv[3]);
        *(uint4*)(smem + H_AH(buf) + off + 16) = make_uint4(hv[4], hv[5], hv[6], hv[7]);
        *(uint4*)(smem + H_AL(buf) + off)      = make_uint4(lv[0], lv[1], lv[2], lv[3]);
        *(uint4*)(smem + H_AL(buf) + off + 16) = make_uint4(lv[4], lv[5], lv[6], lv[7]);
    };
    auto cp_w = [&](int c, int buf) {
#pragma unroll
        for (int it = 0; it < 4; it++) {
            int idx = tid + it * 256;
            int h = idx >> 9, rem = idx & 511;
            int n = rem >> 2, s = rem & 3;
            const char* src = (const char*)(h ? g_wt_lo : g_wt_hi) + (size_t)n * (ND * 2) + c * (KC * 2) + s * 16;
            cp16(smem + (h ? H_BL(buf) : H_BH(buf)) + n * (ASTR * 2) + s * 16, src);
        }
        cp_commit();
    };

    float acc[2][8][4];
#pragma unroll
    for (int m = 0; m < 2; m++)
#pragma unroll
        for (int nf = 0; nf < 8; nf++)
#pragma unroll
            for (int e = 0; e < 4; e++) acc[m][nf][e] = 0.0f;

    const uint32_t lane_off = (uint32_t)((l & 15) * (ASTR * 2) + (l >> 4) * 16);

    // ---- prologue: W-independent work first, then wait for wprep ----
    load_x(0);
#if __CUDA_ARCH__ >= 900
    cudaGridDependencySynchronize();     // g_wt_hi/lo ready past this point
#endif
    cp_w(0, 0);
    sts_x(0);

#pragma unroll 1
    for (int c = 0; c < NCHUNK; c++) {
        const int buf = c & 1;
        cp_wait<0>();          // drain group c (the only outstanding one)
        __syncthreads();       // B(c)+A(c) visible; all iter c-1 reads retired
        if (c < NCHUNK - 1) {  // stage chunk c+1 AFTER the barrier: race-free
            cp_w(c + 1, buf ^ 1);
            load_x(c + 1);
        }

        const uint32_t ah_base = smb + H_AH(buf) + (uint32_t)(wm * 32) * (ASTR * 2) + lane_off;
        const uint32_t al_base = smb + H_AL(buf) + (uint32_t)(wm * 32) * (ASTR * 2) + lane_off;
        const uint32_t bh_base = smb + H_BH(buf) + (uint32_t)(wn * 64) * (ASTR * 2) + lane_off;
        const uint32_t bl_base = smb + H_BL(buf) + (uint32_t)(wn * 64) * (ASTR * 2) + lane_off;

#pragma unroll
        for (int kk = 0; kk < KC; kk += 16) {
            uint32_t ah[2][4], al[2][4];
#pragma unroll
            for (int m = 0; m < 2; m++) {
                LDSM4(ah[m], ah_base + m * 16 * (ASTR * 2) + kk * 2);
                LDSM4(al[m], al_base + m * 16 * (ASTR * 2) + kk * 2);
            }
#pragma unroll
            for (int np = 0; np < 4; np++) {
                uint32_t bh[4], bl[4];
                LDSM4(bh, bh_base + np * 16 * (ASTR * 2) + kk * 2);
                LDSM4(bl, bl_base + np * 16 * (ASTR * 2) + kk * 2);
#pragma unroll
                for (int m = 0; m < 2; m++)
#pragma unroll
                    for (int sn = 0; sn < 2; sn++) {
                        float* d = acc[m][np * 2 + sn];
                        uint32_t h0 = sn ? bh[1] : bh[0], h1 = sn ? bh[3] : bh[2];
                        uint32_t l0 = sn ? bl[1] : bl[0], l1 = sn ? bl[3] : bl[2];
                        MMA16816(d, ah[m], h0, h1);
                        MMA16816(d, ah[m], l0, l1);
                        MMA16816(d, al[m], h0, h1);
                    }
            }
        }
        if (c < NCHUNK - 1) sts_x(buf ^ 1);   // readers gated by next top barrier
    }

    // ---- epilogue: tanh + dot(u) ----
    __syncthreads();
    const int g = l >> 2, tig = l & 3;
#pragma unroll
    for (int m = 0; m < 2; m++) {
        float pA = 0.0f, pB = 0.0f;
#pragma unroll
        for (int nf = 0; nf < 8; nf++)
#pragma unroll
            for (int e = 0; e < 2; e++) {
                int col = wn * 64 + nf * 8 + 2 * tig + e;
                pA += fast_tanh(acc[m][nf][e]     + bsm[col]) * usm[col];
                pB += fast_tanh(acc[m][nf][2 + e] + bsm[col]) * usm[col];
            }
        pA += __shfl_xor_sync(0xffffffffu, pA, 1);
        pA += __shfl_xor_sync(0xffffffffu, pA, 2);
        pB += __shfl_xor_sync(0xffffffffu, pB, 1);
        pB += __shfl_xor_sync(0xffffffffu, pB, 2);
        if (tig == 0) {
            int row = wm * 32 + m * 16 + g;
            atomicAdd(&red[row], pA);          // exactly 2 contributors/row
            atomicAdd(&red[row + 8], pB);
        }
    }
    __syncthreads();
    if (tid < TS) es[tid] = expf(red[tid]);    // faithful: no max-subtraction
    __syncthreads();

    // tile exp-sum (deterministic tree)
    if (tid < 64) red[tid] = es[tid] + es[tid + 64];
    __syncthreads();
    if (tid < 32) {
        float v = red[tid] + red[tid + 32];
#pragma unroll
        for (int off = 16; off > 0; off >>= 1)
            v += __shfl_down_sync(0xffffffffu, v, off);
        if (tid == 0) g_esum[b * NTILE + tile] = v;
    }

    // weighted partial sum over tile rows (x L2-hot)
    float a0 = 0.f, a1 = 0.f, a2 = 0.f, a3 = 0.f;
#pragma unroll 4
    for (int s = 0; s < TS; s += 4) {
        a0 += es[s + 0] * xb[(size_t)(s + 0) * ND + tid];
        a1 += es[s + 1] * xb[(size_t)(s + 1) * ND + tid];
        a2 += es[s + 2] * xb[(size_t)(s + 2) * ND + tid];
        a3 += es[s + 3] * xb[(size_t)(s + 3) * ND + tid];
    }
    g_part[((size_t)b * NTILE + tile) * ND + tid] = (a0 + a1) + (a2 + a3);

#if __CUDA_ARCH__ >= 900
    cudaTriggerProgrammaticLaunchCompletion();   // writes above visible to finish after its gridsync
#endif
}

// ---------------------------------------------------------------------------
__global__ void __launch_bounds__(256) finish_kernel(float* __restrict__ out)
{
#if __CUDA_ARCH__ >= 900
    cudaGridDependencySynchronize();    // all scores blocks triggered; g_part/g_esum visible
#endif
    const int b = blockIdx.x;
    const int tid = threadIdx.x;
    float s = 0.f;
#pragma unroll
    for (int t = 0; t < NTILE; t++) s += g_esum[b * NTILE + t];
    const float inv = 1.0f / (s + 1e-8f);
    float v = 0.f;
#pragma unroll
    for (int t = 0; t < NTILE; t++) v += g_part[((size_t)b * NTILE + t) * ND + tid];
    out[b * ND + tid] = v * inv;
}

extern "C" void kernel_launch(void* const* d_in, const int* in_sizes, int n_in,
                              void* d_out, int out_size) {
    const float* x    = (const float*)d_in[0];
    const float* W    = (const float*)d_in[1];
    const float* bias = (const float*)d_in[2];
    const float* u    = (const float*)d_in[3];
    float* out        = (float*)d_out;

    cudaFuncSetAttribute(scores_kernel, cudaFuncAttributeMaxDynamicSharedMemorySize, SMEM_TOTAL);

    wprep_kernel<<<(ND * NA + 255) / 256, 256>>>(W);

    cudaLaunchAttribute pdl[1];
    pdl[0].id = cudaLaunchAttributeProgrammaticStreamSerialization;
    pdl[0].val.programmaticStreamSerializationAllowed = 1;

    cudaLaunchConfig_t cfg1 = {};
    cfg1.gridDim = dim3(NTILE, NB);
    cfg1.blockDim = dim3(256);
    cfg1.dynamicSmemBytes = SMEM_TOTAL;
    cfg1.stream = 0;
    cfg1.attrs = pdl;
    cfg1.numAttrs = 1;
    cudaLaunchKernelEx(&cfg1, scores_kernel, x, bias, u);

    cudaLaunchConfig_t cfg2 = {};
    cfg2.gridDim = dim3(NB);
    cfg2.blockDim = dim3(256);
    cfg2.stream = 0;
    cfg2.attrs = pdl;
    cfg2.numAttrs = 1;
    cudaLaunchKernelEx(&cfg2, finish_kernel, out);
}